// round 12
// baseline (speedup 1.0000x reference)
#include <cuda_runtime.h>
#include <cstdint>

#define Bz  8
#define Sz  256
#define Hz  128
#define HDz 32
#define BSz 2048
#define SCALE 0.17677669529663687f   // 1/sqrt(32)
#define TST 132                       // rel tile row stride (floats)
#define XPAD 129                      // proj input row stride (conflict-free lane-per-row)

// __device__ scratch (allocation-free rule)
__device__ float g_Q[BSz * Hz];
__device__ float g_Keff[BSz * Hz];
__device__ float g_Veff[BSz * Hz];
__device__ float g_u[Bz * 2 * Sz * Hz];        // u[b,i,q][128]
__device__ float g_sbase[Bz * 4 * Sz * Sz];    // rel heads only: [b][h][q][k]
__device__ float g_probs[Bz * 4 * Sz * Sz];    // abs: normalized; rel: pexp (scaled in ctxv)
__device__ float g_mred[Bz * 2 * Sz * 2 * 2];  // (m,l) per (b,i,q,half)
__device__ float g_wpart[Bz * 2 * Sz * 2 * Hz];// wacc per (b,i,q,half)[128]
__device__ float g_M[2 * Hz * Hz];             // M_i = Wv_hr-slice @ Wo_hr-rows
__device__ float g_bvo[Hz];                    // bo + sum bv_hr @ Wo_hr-rows
__device__ float g_ctx[BSz * Hz];

#define CP_ASYNC16(dst, src) \
    asm volatile("cp.async.cg.shared.global [%0], [%1], 16;\n" :: "r"(dst), "l"(src))
#define CP_COMMIT() asm volatile("cp.async.commit_group;\n" ::: "memory")
#define CP_WAIT0()  asm volatile("cp.async.wait_group 0;\n" ::: "memory")

// ---------------------------------------------------------------------------
// K0: projections, register-tiled. CTAs 0..127: 16 rows each.
// CTAs 128..129: precompute M_i = Wv[:,hr]·Wo[hr,:]  (+ bvo in CTA 129).
// ---------------------------------------------------------------------------
__global__ void __launch_bounds__(256, 2) proj_kernel(
        const float* __restrict__ X,
        const float* __restrict__ abs0,
        const float* __restrict__ abs1,
        const float* __restrict__ Wq, const float* __restrict__ bq,
        const float* __restrict__ Wk, const float* __restrict__ bk,
        const float* __restrict__ Wv, const float* __restrict__ bv,
        const float* __restrict__ Wo, const float* __restrict__ bo) {
    int t = threadIdx.x;
    extern __shared__ float smp[];

    if (blockIdx.x >= 128) {
        // ---- M precompute CTA ----
        int i = blockIdx.x - 128, hr = 2 + i;
        float* wo_s = smp;               // 32*128
        float* wv_s = smp + 32 * Hz;     // 128*33
        #pragma unroll
        for (int jj = 0; jj < 16; jj++) {
            int idx = jj * 256 + t;      // 4096
            int c = idx >> 7, j = idx & 127;
            wo_s[idx] = Wo[(hr * HDz + c) * Hz + j];
        }
        #pragma unroll
        for (int jj = 0; jj < 16; jj++) {
            int idx = jj * 256 + t;      // 4096
            int ch = idx >> 5, c = idx & 31;
            wv_s[ch * 33 + c] = Wv[ch * Hz + hr * HDz + c];
        }
        __syncthreads();

        int tx = t & 15, ty = t >> 4;    // 16x16 thread grid
        int jb = tx * 8, chb = ty * 8;
        float acc[8][8];
        #pragma unroll
        for (int r = 0; r < 8; r++)
            #pragma unroll
            for (int cc = 0; cc < 8; cc++) acc[r][cc] = 0.f;
        #pragma unroll 4
        for (int c = 0; c < 32; c++) {
            float av[8], bx[8];
            #pragma unroll
            for (int r = 0; r < 8; r++) av[r] = wv_s[(chb + r) * 33 + c];
            *(float4*)&bx[0] = *(float4*)&wo_s[c * Hz + jb];
            *(float4*)&bx[4] = *(float4*)&wo_s[c * Hz + jb + 4];
            #pragma unroll
            for (int r = 0; r < 8; r++)
                #pragma unroll
                for (int cc = 0; cc < 8; cc++)
                    acc[r][cc] += av[r] * bx[cc];
        }
        #pragma unroll
        for (int r = 0; r < 8; r++) {
            *(float4*)&g_M[i * Hz * Hz + (chb + r) * Hz + jb]     = *(float4*)&acc[r][0];
            *(float4*)&g_M[i * Hz * Hz + (chb + r) * Hz + jb + 4] = *(float4*)&acc[r][4];
        }
        if (i == 1 && t < Hz) {
            float a = bo[t];
            #pragma unroll 8
            for (int c = 0; c < 64; c++)
                a += bv[64 + c] * Wo[(64 + c) * Hz + t];
            g_bvo[t] = a;
        }
        return;
    }

    int r0 = blockIdx.x * 16;
    float* xs  = smp;                    // 16 * XPAD
    float* a0s = xs  + 16 * XPAD;
    float* a1s = a0s + 16 * XPAD;
    float* wts = a1s + 16 * XPAD;        // 3 * 32 * 128

    #pragma unroll
    for (int jj = 0; jj < 8; jj++) {
        int idx = jj * 256 + t;
        int row = idx >> 7, col = idx & 127;
        xs [row * XPAD + col] = X   [(r0 + row) * Hz + col];
        a0s[row * XPAD + col] = abs0[(r0 + row) * Hz + col];
        a1s[row * XPAD + col] = abs1[(r0 + row) * Hz + col];
    }

    int r = t & 15, jg = t >> 4;
    int j0 = jg * 8;
    bool fold = (jg < 8);
    const float* as = (jg < 4) ? a0s : a1s;

    float qa[8], ka[8], va[8];
    #pragma unroll
    for (int jj = 0; jj < 8; jj++) {
        qa[jj] = bq[j0 + jj];
        float bkv = bk[j0 + jj], bvv = bv[j0 + jj];
        ka[jj] = fold ? 2.f * bkv : bkv;
        va[jj] = fold ? 2.f * bvv : bvv;
    }

    for (int i0 = 0; i0 < Hz; i0 += 32) {
        __syncthreads();
        #pragma unroll
        for (int jj = 0; jj < 4; jj++) {
            int idx = jj * 256 + t;
            ((float4*)wts)[idx]               = ((const float4*)(Wq + i0 * Hz))[idx];
            ((float4*)(wts + 32 * Hz))[idx]   = ((const float4*)(Wk + i0 * Hz))[idx];
            ((float4*)(wts + 64 * Hz))[idx]   = ((const float4*)(Wv + i0 * Hz))[idx];
        }
        __syncthreads();
        #pragma unroll 8
        for (int ii = 0; ii < 32; ii++) {
            int i = i0 + ii;
            float x = xs[r * XPAD + i];
            float wq[8], wk8[8], wv8[8];
            *(float4*)&wq [0] = *(const float4*)&wts[ii * Hz + j0];
            *(float4*)&wq [4] = *(const float4*)&wts[ii * Hz + j0 + 4];
            *(float4*)&wk8[0] = *(const float4*)&wts[32 * Hz + ii * Hz + j0];
            *(float4*)&wk8[4] = *(const float4*)&wts[32 * Hz + ii * Hz + j0 + 4];
            *(float4*)&wv8[0] = *(const float4*)&wts[64 * Hz + ii * Hz + j0];
            *(float4*)&wv8[4] = *(const float4*)&wts[64 * Hz + ii * Hz + j0 + 4];
            #pragma unroll
            for (int jj = 0; jj < 8; jj++) {
                qa[jj] += x * wq[jj];
                ka[jj] += x * wk8[jj];
                va[jj] += x * wv8[jj];
            }
            if (fold) {
                float a = as[r * XPAD + i];
                #pragma unroll
                for (int jj = 0; jj < 8; jj++) {
                    ka[jj] += a * wk8[jj];
                    va[jj] += a * wv8[jj];
                }
            }
        }
    }

    int ro = r0 + r;
    *(float4*)&g_Q[ro * Hz + j0]        = *(float4*)&qa[0];
    *(float4*)&g_Q[ro * Hz + j0 + 4]    = *(float4*)&qa[4];
    *(float4*)&g_Keff[ro * Hz + j0]     = *(float4*)&ka[0];
    *(float4*)&g_Keff[ro * Hz + j0 + 4] = *(float4*)&ka[4];
    *(float4*)&g_Veff[ro * Hz + j0]     = *(float4*)&va[0];
    *(float4*)&g_Veff[ro * Hz + j0 + 4] = *(float4*)&va[4];
}

// ---------------------------------------------------------------------------
// K1: scores. Rel heads (h>=2): write sbase AND u-vectors. Abs heads (h<2):
// finish softmax in-CTA, write NORMALIZED probs. grid (8,8,4), 256 threads.
// ---------------------------------------------------------------------------
__global__ void __launch_bounds__(256) sbase_kernel(const float* __restrict__ mask,
                                                    const float* __restrict__ Wk) {
    int qt = blockIdx.x, b = blockIdx.y, h = blockIdx.z;
    int t = threadIdx.x;
    extern __shared__ float smb[];
    float* Qs = smb;                  // 32*32
    float* ks = Qs + 32 * 32;         // 256*33
    float* ss = ks + 256 * 33;        // 32*257 (abs only)

    #pragma unroll
    for (int r = 0; r < 4; r++) {
        int idx = r * 256 + t;
        int qq = idx >> 5, c = idx & 31;
        Qs[idx] = g_Q[(b * Sz + qt * 32 + qq) * Hz + h * HDz + c];
    }
    #pragma unroll
    for (int jj = 0; jj < 8; jj++) {
        int idx = jj * 256 + t;
        int row = idx >> 3, c4 = idx & 7;
        float4 v = *(const float4*)&g_Keff[(b * Sz + row) * Hz + h * HDz + c4 * 4];
        ks[row * 33 + c4 * 4 + 0] = v.x;
        ks[row * 33 + c4 * 4 + 1] = v.y;
        ks[row * 33 + c4 * 4 + 2] = v.z;
        ks[row * 33 + c4 * 4 + 3] = v.w;
    }
    __syncthreads();

    float kr[32];
    #pragma unroll
    for (int c = 0; c < 32; c++) kr[c] = ks[t * 33 + c];

    int qbase = qt * 32;
    if (h >= 2) {
        #pragma unroll 2
        for (int qq = 0; qq < 32; qq++) {
            float acc = 0.f;
            #pragma unroll
            for (int c = 0; c < 32; c++) acc += Qs[qq * 32 + c] * kr[c];
            int q = qbase + qq;
            g_sbase[((b * 4 + h) * Sz + q) * Sz + t] =
                acc * SCALE + mask[(b * Sz + q) * Sz + t];
        }
        int j = t & 127, g2 = t >> 7;
        int i = h - 2;
        float wr[32];
        #pragma unroll
        for (int c4 = 0; c4 < 8; c4++)
            *(float4*)&wr[c4 * 4] = *(const float4*)&Wk[j * Hz + h * HDz + c4 * 4];
        #pragma unroll 4
        for (int qq = g2 * 16; qq < g2 * 16 + 16; qq++) {
            float acc = 0.f;
            #pragma unroll
            for (int c = 0; c < 32; c++) acc += wr[c] * Qs[qq * 32 + c];
            g_u[((b * 2 + i) * Sz + qbase + qq) * Hz + j] = acc;
        }
    } else {
        #pragma unroll 2
        for (int qq = 0; qq < 32; qq++) {
            float acc = 0.f;
            #pragma unroll
            for (int c = 0; c < 32; c++) acc += Qs[qq * 32 + c] * kr[c];
            int q = qbase + qq;
            ss[qq * 257 + t] = acc * SCALE + mask[(b * Sz + q) * Sz + t];
        }
        __syncthreads();
        int w = t >> 5, lane = t & 31;
        #pragma unroll
        for (int r = 0; r < 4; r++) {
            int row = w * 4 + r;
            float v[8];
            #pragma unroll
            for (int j = 0; j < 8; j++) v[j] = ss[row * 257 + lane + j * 32];
            float m = v[0];
            #pragma unroll
            for (int j = 1; j < 8; j++) m = fmaxf(m, v[j]);
            #pragma unroll
            for (int o = 16; o; o >>= 1) m = fmaxf(m, __shfl_xor_sync(~0u, m, o));
            float p[8], l = 0.f;
            #pragma unroll
            for (int j = 0; j < 8; j++) { p[j] = __expf(v[j] - m); l += p[j]; }
            #pragma unroll
            for (int o = 16; o; o >>= 1) l += __shfl_xor_sync(~0u, l, o);
            float inv = 1.f / l;
            int q = qbase + row;
            #pragma unroll
            for (int j = 0; j < 8; j++)
                g_probs[((b * 4 + h) * Sz + q) * Sz + lane + j * 32] = p[j] * inv;
        }
    }
}

// ---------------------------------------------------------------------------
// K2: rel split-K (halves). CTA per (q, b, i*2+half); 128 threads (4 warps).
// (unchanged — 86us @ 81% DRAM, at roofline)
// ---------------------------------------------------------------------------
__global__ void __launch_bounds__(128, 3) rel_kernel(
        const float* __restrict__ rel0, const float* __restrict__ rel1) {
    int q = blockIdx.x, b = blockIdx.y;
    int i = blockIdx.z >> 1, half = blockIdx.z & 1;
    int hr = 2 + i;
    int kbase = half * 128;
    int t = threadIdx.x, lane = t & 31, w = t >> 5;

    extern __shared__ float sm[];
    float* tile = sm;                 // [128][TST]
    float* uvec = sm + 128 * TST;     // 128
    float* kb   = uvec + 128;         // 128
    float* pc   = kb + 128;           // 128
    float* wm   = pc + 128;           // 4
    float* wl   = wm + 4;             // 4

    const float4* rp4 = (const float4*)(((i == 0) ? rel0 : rel1)
                        + (size_t)(b * Sz + q) * Sz * Hz) + (size_t)kbase * 32;
    uint32_t tileu = (uint32_t)__cvta_generic_to_shared(tile);
    #pragma unroll
    for (int r = 0; r < 32; r++) {
        int row = w * 32 + r;
        uint32_t d = tileu + (uint32_t)(row * TST + lane * 4) * 4;
        CP_ASYNC16(d, rp4 + row * 32 + lane);
    }
    CP_COMMIT();

    uvec[t] = g_u[((b * 2 + i) * Sz + q) * Hz + t];
    kb[t]   = g_sbase[((b * 4 + hr) * Sz + q) * Sz + kbase + t];
    __syncthreads();

    CP_WAIT0();
    __syncwarp();
    float s;
    {
        const float4* row = (const float4*)&tile[t * TST];
        const float4* u4  = (const float4*)uvec;
        float acc = 0.f;
        #pragma unroll
        for (int j = 0; j < 32; j++) {
            float4 r = row[j], u = u4[j];
            acc += r.x * u.x + r.y * u.y + r.z * u.z + r.w * u.w;
        }
        s = acc * SCALE + kb[t];
    }
    float mw = s;
    #pragma unroll
    for (int o = 16; o; o >>= 1) mw = fmaxf(mw, __shfl_xor_sync(~0u, mw, o));
    if (lane == 0) wm[w] = mw;
    __syncthreads();

    float M = fmaxf(fmaxf(wm[0], wm[1]), fmaxf(wm[2], wm[3]));
    float p = __expf(s - M);
    pc[t] = p;
    float lw = p;
    #pragma unroll
    for (int o = 16; o; o >>= 1) lw += __shfl_xor_sync(~0u, lw, o);
    if (lane == 0) wl[w] = lw;
    __syncthreads();
    float L = wl[0] + wl[1] + wl[2] + wl[3];

    g_probs[((b * 4 + hr) * Sz + q) * Sz + kbase + t] = p;
    if (t == 0) {
        int mi = ((b * 2 + i) * Sz + q) * 2 + half;
        g_mred[mi * 2 + 0] = M;
        g_mred[mi * 2 + 1] = L;
    }

    {
        float wacc = 0.f;
        #pragma unroll 8
        for (int k = 0; k < 128; k++)
            wacc += pc[k] * tile[k * TST + t];
        g_wpart[(((b * 2 + i) * Sz + q) * 2 + half) * Hz + t] = wacc;
    }
}

// ---------------------------------------------------------------------------
// K3: ctx = probs(scaled) @ Veff. grid (16,8,4), 256 thr, 16 q/CTA.
// Rel heads compute split-K scales from g_mred in-CTA (cheap).
// ---------------------------------------------------------------------------
__global__ void __launch_bounds__(256) ctxv_kernel() {
    int qt = blockIdx.x, b = blockIdx.y, h = blockIdx.z;
    int qbase = qt * 16;
    int t = threadIdx.x;
    extern __shared__ float sm3[];
    float* Vs   = sm3;                        // 256*33
    float* Ps   = sm3 + 256 * 33;             // 16*256
    float* misc = sm3 + 256 * 33 + 16 * 256;  // 96: scales[32], mraw[64]

    if (h >= 2 && t < 64)
        misc[32 + t] = g_mred[((b * 2 + (h - 2)) * Sz + qbase) * 4 + t];
    #pragma unroll
    for (int jj = 0; jj < 8; jj++) {
        int idx = jj * 256 + t;
        int row = idx >> 3, c4 = idx & 7;
        float4 v = *(const float4*)&g_Veff[(b * Sz + row) * Hz + h * HDz + c4 * 4];
        Vs[row * 33 + c4 * 4 + 0] = v.x;
        Vs[row * 33 + c4 * 4 + 1] = v.y;
        Vs[row * 33 + c4 * 4 + 2] = v.z;
        Vs[row * 33 + c4 * 4 + 3] = v.w;
    }
    __syncthreads();
    if (h >= 2 && t < 16) {
        float m0 = misc[32 + t * 4 + 0], l0 = misc[32 + t * 4 + 1];
        float m1 = misc[32 + t * 4 + 2], l1 = misc[32 + t * 4 + 3];
        float M = fmaxf(m0, m1);
        float c0 = __expf(m0 - M), c1 = __expf(m1 - M);
        float invL = 1.f / (l0 * c0 + l1 * c1);
        misc[t]      = c0 * invL;
        misc[16 + t] = c1 * invL;
    }
    __syncthreads();
    #pragma unroll
    for (int jj = 0; jj < 4; jj++) {
        int idx = jj * 256 + t;                  // 1024 float4
        int qq = idx >> 6, k4 = idx & 63;
        float4 v = *(const float4*)&g_probs[((b * 4 + h) * Sz + qbase + qq) * Sz + k4 * 4];
        if (h >= 2) {
            float sc = (k4 >= 32) ? misc[16 + qq] : misc[qq];
            v.x *= sc; v.y *= sc; v.z *= sc; v.w *= sc;
        }
        *(float4*)&Ps[qq * 256 + k4 * 4] = v;
    }
    __syncthreads();

    int c = t & 31, g = t >> 5;                  // 8 groups x 2 q each
    const float4* Ps4 = (const float4*)Ps;
    float acc0 = 0.f, acc1 = 0.f;
    #pragma unroll 4
    for (int k4 = 0; k4 < 64; k4++) {
        float v0 = Vs[(k4 * 4 + 0) * 33 + c];
        float v1 = Vs[(k4 * 4 + 1) * 33 + c];
        float v2 = Vs[(k4 * 4 + 2) * 33 + c];
        float v3 = Vs[(k4 * 4 + 3) * 33 + c];
        float4 P0 = Ps4[(g * 2 + 0) * 64 + k4];
        float4 P1 = Ps4[(g * 2 + 1) * 64 + k4];
        acc0 += P0.x * v0 + P0.y * v1 + P0.z * v2 + P0.w * v3;
        acc1 += P1.x * v0 + P1.y * v1 + P1.z * v2 + P1.w * v3;
    }
    #pragma unroll
    for (int r = 0; r < 2; r++) {
        int q = qbase + g * 2 + r;
        float a = (r == 0) ? acc0 : acc1;
        g_ctx[(b * Sz + q) * Hz + h * HDz + c] = a;
    }
}

// ---------------------------------------------------------------------------
// K4: out = ctx @ Wo + wfin0·M0 + wfin1·M1 + bvo. 16 rows/CTA, 256 threads.
// wfin merged in-CTA from g_wpart with scales recomputed from g_mred.
// ---------------------------------------------------------------------------
__global__ void __launch_bounds__(256) out_kernel(const float* __restrict__ Wo,
                                                  float* __restrict__ out) {
    int r0 = blockIdx.x * 16;
    int b = r0 >> 8;
    int t = threadIdx.x;
    extern __shared__ float sm4[];
    float* ws   = sm4;                   // 128*128 = 16384
    float* xs   = ws + Hz * Hz;          // 16*128  = 2048
    float* wfin = xs + 16 * Hz;          // 2*16*132 = 4224
    float* sc   = wfin + 2 * 16 * 132;   // 64

    #pragma unroll
    for (int jj = 0; jj < 16; jj++) {
        int idx = jj * 256 + t;
        *(float4*)&ws[idx * 4] = *(const float4*)&Wo[idx * 4];
    }
    #pragma unroll
    for (int jj = 0; jj < 2; jj++) {
        int idx = jj * 256 + t;
        *(float4*)&xs[idx * 4] = *(const float4*)&g_ctx[r0 * Hz + idx * 4];
    }
    if (t < 32) {
        int rr = t >> 1, i2 = t & 1;
        int q = (r0 & 255) + rr;
        const float* mr = &g_mred[((b * 2 + i2) * Sz + q) * 4];
        float m0 = mr[0], l0 = mr[1], m1 = mr[2], l1 = mr[3];
        float M = fmaxf(m0, m1);
        float c0 = __expf(m0 - M), c1 = __expf(m1 - M);
        float invL = 1.f / (l0 * c0 + l1 * c1);
        sc[rr * 4 + i2 * 2 + 0] = c0 * invL;
        sc[rr * 4 + i2 * 2 + 1] = c1 * invL;
    }
    __syncthreads();

    // build merged wfin[i][r][ch] (stride 132)
    #pragma unroll
    for (int jj = 0; jj < 16; jj++) {
        int idx = jj * 256 + t;              // 4096
        int i2 = idx >> 11, rr = (idx >> 7) & 15, ch = idx & 127;
        int q = (r0 & 255) + rr;
        int base = ((b * 2 + i2) * Sz + q) * 2 * Hz;
        wfin[i2 * 16 * 132 + rr * 132 + ch] =
            g_wpart[base + ch]      * sc[rr * 4 + i2 * 2 + 0] +
            g_wpart[base + Hz + ch] * sc[rr * 4 + i2 * 2 + 1];
    }
    __syncthreads();

    int j = t & 127, rbase = (t >> 7) * 8;
    float a[8];
    float bj = g_bvo[j];
    #pragma unroll
    for (int r = 0; r < 8; r++) a[r] = bj;
    #pragma unroll 4
    for (int i = 0; i < Hz; i++) {
        float w = ws[i * Hz + j];
        #pragma unroll
        for (int r = 0; r < 8; r++)
            a[r] += xs[(rbase + r) * Hz + i] * w;
    }
    const float* M0 = g_M;
    const float* M1 = g_M + Hz * Hz;
    const float* wf0 = wfin + rbase * 132;
    const float* wf1 = wfin + 16 * 132 + rbase * 132;
    #pragma unroll 4
    for (int ch = 0; ch < Hz; ch++) {
        float m0v = M0[ch * Hz + j];
        float m1v = M1[ch * Hz + j];
        #pragma unroll
        for (int r = 0; r < 8; r++)
            a[r] += wf0[r * 132 + ch] * m0v + wf1[r * 132 + ch] * m1v;
    }
    #pragma unroll
    for (int r = 0; r < 8; r++)
        out[(r0 + rbase + r) * Hz + j] = a[r];
}

// ---------------------------------------------------------------------------
extern "C" void kernel_launch(void* const* d_in, const int* in_sizes, int n_in,
                              void* d_out, int out_size) {
    const float* X    = (const float*)d_in[0];
    const float* mask = (const float*)d_in[1];
    const float* abs0 = (const float*)d_in[2];
    const float* abs1 = (const float*)d_in[3];
    const float* rel0 = (const float*)d_in[4];
    const float* rel1 = (const float*)d_in[5];
    const float* Wq   = (const float*)d_in[6];
    const float* bq   = (const float*)d_in[7];
    const float* Wk   = (const float*)d_in[8];
    const float* bk   = (const float*)d_in[9];
    const float* Wv   = (const float*)d_in[10];
    const float* bv   = (const float*)d_in[11];
    const float* Wo   = (const float*)d_in[12];
    const float* bo   = (const float*)d_in[13];
    float* out = (float*)d_out;

    size_t prsm  = (size_t)(3 * 16 * XPAD + 3 * 32 * Hz) * sizeof(float);
    size_t sbsm  = (size_t)(32 * 32 + 256 * 33 + 32 * 257) * sizeof(float);
    size_t relsm = (size_t)(128 * TST + 128 + 128 + 128 + 4 + 4) * sizeof(float);
    size_t ctxsm = (size_t)(256 * 33 + 16 * 256 + 96) * sizeof(float);
    size_t outsm = (size_t)(Hz * Hz + 16 * Hz + 2 * 16 * 132 + 64) * sizeof(float);
    cudaFuncSetAttribute(proj_kernel,  cudaFuncAttributeMaxDynamicSharedMemorySize, (int)prsm);
    cudaFuncSetAttribute(sbase_kernel, cudaFuncAttributeMaxDynamicSharedMemorySize, (int)sbsm);
    cudaFuncSetAttribute(rel_kernel,   cudaFuncAttributeMaxDynamicSharedMemorySize, (int)relsm);
    cudaFuncSetAttribute(ctxv_kernel,  cudaFuncAttributeMaxDynamicSharedMemorySize, (int)ctxsm);
    cudaFuncSetAttribute(out_kernel,   cudaFuncAttributeMaxDynamicSharedMemorySize, (int)outsm);

    proj_kernel<<<130, 256, prsm>>>(X, abs0, abs1, Wq, bq, Wk, bk, Wv, bv, Wo, bo);
    dim3 gs(8, Bz, 4);
    sbase_kernel<<<gs, 256, sbsm>>>(mask, Wk);
    dim3 gr(Sz, Bz, 4);                        // z = i*2 + half
    rel_kernel<<<gr, 128, relsm>>>(rel0, rel1);
    dim3 gv(16, Bz, 4);
    ctxv_kernel<<<gv, 256, ctxsm>>>();
    out_kernel<<<BSz / 16, 256, outsm>>>(Wo, out);
}

// round 13
// speedup vs baseline: 1.2082x; 1.2082x over previous
#include <cuda_runtime.h>
#include <cstdint>

#define Bz  8
#define Sz  256
#define Hz  128
#define HDz 32
#define BSz 2048
#define SCALE 0.17677669529663687f   // 1/sqrt(32)
#define TST 136                       // 64-row rel tile stride: conflict-free both phases
#define XPAD 129                      // proj input row stride

// __device__ scratch (allocation-free rule)
__device__ float g_Q[BSz * Hz];
__device__ float g_Keff[BSz * Hz];
__device__ float g_Veff[BSz * Hz];
__device__ float g_u[Bz * 2 * Sz * Hz];        // u[b,i,q][128]
__device__ float g_sbase[Bz * 4 * Sz * Sz];    // rel heads only
__device__ float g_probs[Bz * 4 * Sz * Sz];    // abs: normalized; rel: pexp
__device__ float g_pscale[Bz * 4 * Sz * 4];    // rel heads: per (b,h,q,quarter)
__device__ float g_mred[Bz * 2 * Sz * 4 * 2];  // (m,l) per (b,i,q,quarter)
__device__ float g_wpart[Bz * 2 * Sz * 4 * Hz];// wacc per (b,i,q,quarter)[128]
__device__ float g_ctxbase[BSz * Hz];          // rel heads only
__device__ float g_ctx[BSz * Hz];

#define CP_ASYNC16(dst, src) \
    asm volatile("cp.async.cg.shared.global [%0], [%1], 16;\n" :: "r"(dst), "l"(src))
#define CP_COMMIT() asm volatile("cp.async.commit_group;\n" ::: "memory")
#define CP_WAIT0()  asm volatile("cp.async.wait_group 0;\n" ::: "memory")

// ---------------------------------------------------------------------------
// K0: projections, register-tiled. 16 rows/CTA (128 CTAs), 256 threads.
// (identical to R11)
// ---------------------------------------------------------------------------
__global__ void __launch_bounds__(256, 2) proj_kernel(
        const float* __restrict__ X,
        const float* __restrict__ abs0,
        const float* __restrict__ abs1,
        const float* __restrict__ Wq, const float* __restrict__ bq,
        const float* __restrict__ Wk, const float* __restrict__ bk,
        const float* __restrict__ Wv, const float* __restrict__ bv) {
    int r0 = blockIdx.x * 16;
    int t = threadIdx.x;
    extern __shared__ float smp[];
    float* xs  = smp;                    // 16 * XPAD
    float* a0s = xs  + 16 * XPAD;
    float* a1s = a0s + 16 * XPAD;
    float* wts = a1s + 16 * XPAD;        // 3 * 32 * 128

    #pragma unroll
    for (int jj = 0; jj < 8; jj++) {
        int idx = jj * 256 + t;
        int row = idx >> 7, col = idx & 127;
        xs [row * XPAD + col] = X   [(r0 + row) * Hz + col];
        a0s[row * XPAD + col] = abs0[(r0 + row) * Hz + col];
        a1s[row * XPAD + col] = abs1[(r0 + row) * Hz + col];
    }

    int r = t & 15, jg = t >> 4;
    int j0 = jg * 8;
    bool fold = (jg < 8);
    const float* as = (jg < 4) ? a0s : a1s;

    float qa[8], ka[8], va[8];
    #pragma unroll
    for (int jj = 0; jj < 8; jj++) {
        qa[jj] = bq[j0 + jj];
        float bkv = bk[j0 + jj], bvv = bv[j0 + jj];
        ka[jj] = fold ? 2.f * bkv : bkv;
        va[jj] = fold ? 2.f * bvv : bvv;
    }

    for (int i0 = 0; i0 < Hz; i0 += 32) {
        __syncthreads();
        #pragma unroll
        for (int jj = 0; jj < 4; jj++) {
            int idx = jj * 256 + t;
            ((float4*)wts)[idx]               = ((const float4*)(Wq + i0 * Hz))[idx];
            ((float4*)(wts + 32 * Hz))[idx]   = ((const float4*)(Wk + i0 * Hz))[idx];
            ((float4*)(wts + 64 * Hz))[idx]   = ((const float4*)(Wv + i0 * Hz))[idx];
        }
        __syncthreads();
        #pragma unroll 8
        for (int ii = 0; ii < 32; ii++) {
            int i = i0 + ii;
            float x = xs[r * XPAD + i];
            float wq[8], wk8[8], wv8[8];
            *(float4*)&wq [0] = *(const float4*)&wts[ii * Hz + j0];
            *(float4*)&wq [4] = *(const float4*)&wts[ii * Hz + j0 + 4];
            *(float4*)&wk8[0] = *(const float4*)&wts[32 * Hz + ii * Hz + j0];
            *(float4*)&wk8[4] = *(const float4*)&wts[32 * Hz + ii * Hz + j0 + 4];
            *(float4*)&wv8[0] = *(const float4*)&wts[64 * Hz + ii * Hz + j0];
            *(float4*)&wv8[4] = *(const float4*)&wts[64 * Hz + ii * Hz + j0 + 4];
            #pragma unroll
            for (int jj = 0; jj < 8; jj++) {
                qa[jj] += x * wq[jj];
                ka[jj] += x * wk8[jj];
                va[jj] += x * wv8[jj];
            }
            if (fold) {
                float a = as[r * XPAD + i];
                #pragma unroll
                for (int jj = 0; jj < 8; jj++) {
                    ka[jj] += a * wk8[jj];
                    va[jj] += a * wv8[jj];
                }
            }
        }
    }

    int ro = r0 + r;
    *(float4*)&g_Q[ro * Hz + j0]        = *(float4*)&qa[0];
    *(float4*)&g_Q[ro * Hz + j0 + 4]    = *(float4*)&qa[4];
    *(float4*)&g_Keff[ro * Hz + j0]     = *(float4*)&ka[0];
    *(float4*)&g_Keff[ro * Hz + j0 + 4] = *(float4*)&ka[4];
    *(float4*)&g_Veff[ro * Hz + j0]     = *(float4*)&va[0];
    *(float4*)&g_Veff[ro * Hz + j0 + 4] = *(float4*)&va[4];
}

// ---------------------------------------------------------------------------
// K1: scores (identical to R11). Rel heads: sbase + u. Abs heads: softmax.
// ---------------------------------------------------------------------------
__global__ void __launch_bounds__(256) sbase_kernel(const float* __restrict__ mask,
                                                    const float* __restrict__ Wk) {
    int qt = blockIdx.x, b = blockIdx.y, h = blockIdx.z;
    int t = threadIdx.x;
    extern __shared__ float smb[];
    float* Qs = smb;                  // 32*32
    float* ks = Qs + 32 * 32;         // 256*33
    float* ss = ks + 256 * 33;        // 32*257 (abs only)

    #pragma unroll
    for (int r = 0; r < 4; r++) {
        int idx = r * 256 + t;
        int qq = idx >> 5, c = idx & 31;
        Qs[idx] = g_Q[(b * Sz + qt * 32 + qq) * Hz + h * HDz + c];
    }
    #pragma unroll
    for (int jj = 0; jj < 8; jj++) {
        int idx = jj * 256 + t;
        int row = idx >> 3, c4 = idx & 7;
        float4 v = *(const float4*)&g_Keff[(b * Sz + row) * Hz + h * HDz + c4 * 4];
        ks[row * 33 + c4 * 4 + 0] = v.x;
        ks[row * 33 + c4 * 4 + 1] = v.y;
        ks[row * 33 + c4 * 4 + 2] = v.z;
        ks[row * 33 + c4 * 4 + 3] = v.w;
    }
    __syncthreads();

    float kr[32];
    #pragma unroll
    for (int c = 0; c < 32; c++) kr[c] = ks[t * 33 + c];

    int qbase = qt * 32;
    if (h >= 2) {
        #pragma unroll 2
        for (int qq = 0; qq < 32; qq++) {
            float acc = 0.f;
            #pragma unroll
            for (int c = 0; c < 32; c++) acc += Qs[qq * 32 + c] * kr[c];
            int q = qbase + qq;
            g_sbase[((b * 4 + h) * Sz + q) * Sz + t] =
                acc * SCALE + mask[(b * Sz + q) * Sz + t];
        }
        int j = t & 127, g2 = t >> 7;
        int i = h - 2;
        float wr[32];
        #pragma unroll
        for (int c4 = 0; c4 < 8; c4++)
            *(float4*)&wr[c4 * 4] = *(const float4*)&Wk[j * Hz + h * HDz + c4 * 4];
        #pragma unroll 4
        for (int qq = g2 * 16; qq < g2 * 16 + 16; qq++) {
            float acc = 0.f;
            #pragma unroll
            for (int c = 0; c < 32; c++) acc += wr[c] * Qs[qq * 32 + c];
            g_u[((b * 2 + i) * Sz + qbase + qq) * Hz + j] = acc;
        }
    } else {
        #pragma unroll 2
        for (int qq = 0; qq < 32; qq++) {
            float acc = 0.f;
            #pragma unroll
            for (int c = 0; c < 32; c++) acc += Qs[qq * 32 + c] * kr[c];
            int q = qbase + qq;
            ss[qq * 257 + t] = acc * SCALE + mask[(b * Sz + q) * Sz + t];
        }
        __syncthreads();
        int w = t >> 5, lane = t & 31;
        #pragma unroll
        for (int r = 0; r < 4; r++) {
            int row = w * 4 + r;
            float v[8];
            #pragma unroll
            for (int j = 0; j < 8; j++) v[j] = ss[row * 257 + lane + j * 32];
            float m = v[0];
            #pragma unroll
            for (int j = 1; j < 8; j++) m = fmaxf(m, v[j]);
            #pragma unroll
            for (int o = 16; o; o >>= 1) m = fmaxf(m, __shfl_xor_sync(~0u, m, o));
            float p[8], l = 0.f;
            #pragma unroll
            for (int j = 0; j < 8; j++) { p[j] = __expf(v[j] - m); l += p[j]; }
            #pragma unroll
            for (int o = 16; o; o >>= 1) l += __shfl_xor_sync(~0u, l, o);
            float inv = 1.f / l;
            int q = qbase + row;
            #pragma unroll
            for (int j = 0; j < 8; j++)
                g_probs[((b * 4 + h) * Sz + q) * Sz + lane + j * 32] = p[j] * inv;
        }
    }
}

// ---------------------------------------------------------------------------
// K2: rel split-K (QUARTERS, 64 keys/CTA). CTA per (q, b, i*4+quarter);
// 128 threads. 34KB tile -> 6 CTAs/SM (occ 2x vs halves). u precomputed.
// ---------------------------------------------------------------------------
__global__ void __launch_bounds__(128, 6) rel_kernel(
        const float* __restrict__ rel0, const float* __restrict__ rel1) {
    int q = blockIdx.x, b = blockIdx.y;
    int i = blockIdx.z >> 2, quarter = blockIdx.z & 3;
    int hr = 2 + i;
    int kbase = quarter * 64;
    int t = threadIdx.x, lane = t & 31, w = t >> 5;

    extern __shared__ float sm[];
    float* tile = sm;                 // [64][TST]
    float* uvec = sm + 64 * TST;      // 128
    float* kb   = uvec + 128;         // 64
    float* pc   = kb + 64;            // 64
    float* wm   = pc + 64;            // 4
    float* wl   = wm + 4;             // 4

    // 1) issue all loads: warp w rows 16w..16w+15, lane = float4 col
    const float4* rp4 = (const float4*)(((i == 0) ? rel0 : rel1)
                        + (size_t)(b * Sz + q) * Sz * Hz) + (size_t)kbase * 32;
    uint32_t tileu = (uint32_t)__cvta_generic_to_shared(tile);
    #pragma unroll
    for (int r = 0; r < 16; r++) {
        int row = w * 16 + r;
        uint32_t d = tileu + (uint32_t)(row * TST + lane * 4) * 4;
        CP_ASYNC16(d, rp4 + row * 32 + lane);
    }
    CP_COMMIT();

    // 2) prologue (overlaps DRAM)
    uvec[t] = g_u[((b * 2 + i) * Sz + q) * Hz + t];
    if (t < 64) kb[t] = g_sbase[((b * 4 + hr) * Sz + q) * Sz + kbase + t];
    __syncthreads();

    // 3) per-warp wait + score: key = t>>1, part = t&1 (float4s at stride 8)
    CP_WAIT0();
    __syncwarp();
    int key = t >> 1, part = t & 1;
    float s;
    {
        const float4* row = (const float4*)&tile[key * TST + part * 4];
        const float4* up  = (const float4*)&uvec[part * 4];
        float acc = 0.f;
        #pragma unroll
        for (int j = 0; j < 16; j++) {
            float4 r = row[j * 2], u = up[j * 2];
            acc += r.x * u.x + r.y * u.y + r.z * u.z + r.w * u.w;
        }
        acc += __shfl_xor_sync(~0u, acc, 1);
        s = acc * SCALE + kb[key];
    }
    float mw = s;
    #pragma unroll
    for (int o = 16; o; o >>= 1) mw = fmaxf(mw, __shfl_xor_sync(~0u, mw, o));
    if (lane == 0) wm[w] = mw;
    __syncthreads();

    // 4) quarter-local max, p, quarter-local sum
    float M = fmaxf(fmaxf(wm[0], wm[1]), fmaxf(wm[2], wm[3]));
    float p = __expf(s - M);
    if (part == 0) pc[key] = p;
    float lw = (part == 0) ? p : 0.f;
    #pragma unroll
    for (int o = 16; o; o >>= 1) lw += __shfl_xor_sync(~0u, lw, o);
    if (lane == 0) wl[w] = lw;
    __syncthreads();
    float L = wl[0] + wl[1] + wl[2] + wl[3];

    if (t < 64)
        g_probs[((b * 4 + hr) * Sz + q) * Sz + kbase + t] = pc[t];
    if (t == 0) {
        int mi = ((b * 2 + i) * Sz + q) * 4 + quarter;
        g_mred[mi * 2 + 0] = M;
        g_mred[mi * 2 + 1] = L;
    }

    // 5) wacc[ch] = sum_k pc[k] * tile[k][ch]  (thread = channel)
    {
        float wacc = 0.f;
        #pragma unroll 8
        for (int k = 0; k < 64; k++)
            wacc += pc[k] * tile[k * TST + t];
        g_wpart[(((b * 2 + i) * Sz + q) * 4 + quarter) * Hz + t] = wacc;
    }
}

// ---------------------------------------------------------------------------
// K2b: combine, batched (16 q/CTA), 4-quarter merge. grid (16, Bz, 2).
// ---------------------------------------------------------------------------
__global__ void __launch_bounds__(256) combine_kernel(
        const float* __restrict__ Wv, const float* __restrict__ bv) {
    int qt = blockIdx.x, b = blockIdx.y, i = blockIdx.z;
    int hr = 2 + i;
    int qbase = qt * 16;
    int t = threadIdx.x;

    extern __shared__ float smc[];
    float* wv   = smc;               // 128*33 = 4224
    float* wfin = wv + 128 * 33;     // 16*130 = 2080
    float* misc = wfin + 16 * 130;   // 192: scales[64], mraw[128]

    // (m,l) for 16 q x 4 quarters (128 consecutive floats) + Wv slice
    if (t < 128) misc[64 + t] = g_mred[((b * 2 + i) * Sz + qbase) * 8 + t];
    #pragma unroll
    for (int jj = 0; jj < 4; jj++) {
        int idx = jj * 256 + t;      // 1024 float4
        int row = idx >> 3, c4 = idx & 7;
        float4 v = *(const float4*)&Wv[row * Hz + hr * HDz + c4 * 4];
        wv[row * 33 + c4 * 4 + 0] = v.x;
        wv[row * 33 + c4 * 4 + 1] = v.y;
        wv[row * 33 + c4 * 4 + 2] = v.z;
        wv[row * 33 + c4 * 4 + 3] = v.w;
    }
    __syncthreads();

    if (t < 16) {
        const float* mr = &misc[64 + t * 8];
        float m0 = mr[0], l0 = mr[1], m1 = mr[2], l1 = mr[3];
        float m2 = mr[4], l2 = mr[5], m3 = mr[6], l3 = mr[7];
        float M = fmaxf(fmaxf(m0, m1), fmaxf(m2, m3));
        float c0 = __expf(m0 - M), c1 = __expf(m1 - M);
        float c2 = __expf(m2 - M), c3 = __expf(m3 - M);
        float invL = 1.f / (l0 * c0 + l1 * c1 + l2 * c2 + l3 * c3);
        misc[t * 4 + 0] = c0 * invL;
        misc[t * 4 + 1] = c1 * invL;
        misc[t * 4 + 2] = c2 * invL;
        misc[t * 4 + 3] = c3 * invL;
        g_pscale[((b * 4 + hr) * Sz + qbase + t) * 4 + 0] = c0 * invL;
        g_pscale[((b * 4 + hr) * Sz + qbase + t) * 4 + 1] = c1 * invL;
        g_pscale[((b * 4 + hr) * Sz + qbase + t) * 4 + 2] = c2 * invL;
        g_pscale[((b * 4 + hr) * Sz + qbase + t) * 4 + 3] = c3 * invL;
    }
    __syncthreads();

    // merge wacc quarters (normalized)
    #pragma unroll
    for (int jj = 0; jj < 8; jj++) {
        int idx = jj * 256 + t;      // 2048
        int q = idx >> 7, ch = idx & 127;
        int base = (((b * 2 + i) * Sz + qbase + q) * 4) * Hz;
        wfin[q * 130 + ch] = g_wpart[base + ch]          * misc[q * 4 + 0]
                           + g_wpart[base + Hz + ch]     * misc[q * 4 + 1]
                           + g_wpart[base + 2 * Hz + ch] * misc[q * 4 + 2]
                           + g_wpart[base + 3 * Hz + ch] * misc[q * 4 + 3];
    }
    __syncthreads();

    // projection: thread q = t>>4, 2 channels cc=(t&15)*2
    {
        int q = t >> 4, cc = (t & 15) * 2;
        float a0 = bv[hr * HDz + cc], a1 = bv[hr * HDz + cc + 1];
        #pragma unroll 8
        for (int ch = 0; ch < 128; ch++) {
            float wf = wfin[q * 130 + ch];
            a0 += wf * wv[ch * 33 + cc];
            a1 += wf * wv[ch * 33 + cc + 1];
        }
        g_ctxbase[(b * Sz + qbase + q) * Hz + hr * HDz + cc]     = a0;
        g_ctxbase[(b * Sz + qbase + q) * Hz + hr * HDz + cc + 1] = a1;
    }
}

// ---------------------------------------------------------------------------
// K3: ctx = [ctxbase +] probs(scaled) @ Veff. grid (16,8,4), 256 thr.
// (R11, with 4 scales per q)
// ---------------------------------------------------------------------------
__global__ void __launch_bounds__(256) ctxv_kernel() {
    int qt = blockIdx.x, b = blockIdx.y, h = blockIdx.z;
    int qbase = qt * 16;
    int t = threadIdx.x;
    extern __shared__ float sm3[];
    float* Vs  = sm3;                        // 256*33
    float* Ps  = sm3 + 256 * 33;             // 16*256
    float* psc = sm3 + 256 * 33 + 16 * 256;  // 64

    if (h >= 2 && t < 64)
        psc[t] = g_pscale[((b * 4 + h) * Sz + qbase + (t >> 2)) * 4 + (t & 3)];
    #pragma unroll
    for (int jj = 0; jj < 8; jj++) {
        int idx = jj * 256 + t;
        int row = idx >> 3, c4 = idx & 7;
        float4 v = *(const float4*)&g_Veff[(b * Sz + row) * Hz + h * HDz + c4 * 4];
        Vs[row * 33 + c4 * 4 + 0] = v.x;
        Vs[row * 33 + c4 * 4 + 1] = v.y;
        Vs[row * 33 + c4 * 4 + 2] = v.z;
        Vs[row * 33 + c4 * 4 + 3] = v.w;
    }
    __syncthreads();
    #pragma unroll
    for (int jj = 0; jj < 4; jj++) {
        int idx = jj * 256 + t;                  // 1024 float4
        int qq = idx >> 6, k4 = idx & 63;
        float4 v = *(const float4*)&g_probs[((b * 4 + h) * Sz + qbase + qq) * Sz + k4 * 4];
        if (h >= 2) {
            float sc = psc[qq * 4 + (k4 >> 4)];
            v.x *= sc; v.y *= sc; v.z *= sc; v.w *= sc;
        }
        *(float4*)&Ps[qq * 256 + k4 * 4] = v;
    }
    __syncthreads();

    int c = t & 31, g = t >> 5;                  // 8 groups x 2 q each
    const float4* Ps4 = (const float4*)Ps;
    float acc0 = 0.f, acc1 = 0.f;
    #pragma unroll 4
    for (int k4 = 0; k4 < 64; k4++) {
        float v0 = Vs[(k4 * 4 + 0) * 33 + c];
        float v1 = Vs[(k4 * 4 + 1) * 33 + c];
        float v2 = Vs[(k4 * 4 + 2) * 33 + c];
        float v3 = Vs[(k4 * 4 + 3) * 33 + c];
        float4 P0 = Ps4[(g * 2 + 0) * 64 + k4];
        float4 P1 = Ps4[(g * 2 + 1) * 64 + k4];
        acc0 += P0.x * v0 + P0.y * v1 + P0.z * v2 + P0.w * v3;
        acc1 += P1.x * v0 + P1.y * v1 + P1.z * v2 + P1.w * v3;
    }
    #pragma unroll
    for (int r = 0; r < 2; r++) {
        int q = qbase + g * 2 + r;
        float a = (r == 0) ? acc0 : acc1;
        float base = (h >= 2) ? g_ctxbase[(b * Sz + q) * Hz + h * HDz + c] : 0.f;
        g_ctx[(b * Sz + q) * Hz + h * HDz + c] = base + a;
    }
}

// ---------------------------------------------------------------------------
// K4: out = ctx @ Wo + bo. (identical to R11)
// ---------------------------------------------------------------------------
__global__ void __launch_bounds__(256) out_kernel(const float* __restrict__ Wo,
                                                  const float* __restrict__ bo,
                                                  float* __restrict__ out) {
    int r0 = blockIdx.x * 16;
    int t = threadIdx.x;
    extern __shared__ float sm4[];
    float* ws = sm4;                 // 128*128
    float* xs = sm4 + Hz * Hz;       // 16*128

    #pragma unroll
    for (int jj = 0; jj < 16; jj++) {
        int idx = jj * 256 + t;
        *(float4*)&ws[idx * 4] = *(const float4*)&Wo[idx * 4];
    }
    #pragma unroll
    for (int jj = 0; jj < 2; jj++) {
        int idx = jj * 256 + t;
        *(float4*)&xs[idx * 4] = *(const float4*)&g_ctx[r0 * Hz + idx * 4];
    }
    __syncthreads();

    int j = t & 127, rbase = (t >> 7) * 8;
    float a[8];
    float bj = bo[j];
    #pragma unroll
    for (int r = 0; r < 8; r++) a[r] = bj;
    #pragma unroll 4
    for (int i = 0; i < Hz; i++) {
        float w = ws[i * Hz + j];
        #pragma unroll
        for (int r = 0; r < 8; r++)
            a[r] += xs[(rbase + r) * Hz + i] * w;
    }
    #pragma unroll
    for (int r = 0; r < 8; r++)
        out[(r0 + rbase + r) * Hz + j] = a[r];
}

// ---------------------------------------------------------------------------
extern "C" void kernel_launch(void* const* d_in, const int* in_sizes, int n_in,
                              void* d_out, int out_size) {
    const float* X    = (const float*)d_in[0];
    const float* mask = (const float*)d_in[1];
    const float* abs0 = (const float*)d_in[2];
    const float* abs1 = (const float*)d_in[3];
    const float* rel0 = (const float*)d_in[4];
    const float* rel1 = (const float*)d_in[5];
    const float* Wq   = (const float*)d_in[6];
    const float* bq   = (const float*)d_in[7];
    const float* Wk   = (const float*)d_in[8];
    const float* bk   = (const float*)d_in[9];
    const float* Wv   = (const float*)d_in[10];
    const float* bv   = (const float*)d_in[11];
    const float* Wo   = (const float*)d_in[12];
    const float* bo   = (const float*)d_in[13];
    float* out = (float*)d_out;

    size_t prsm  = (size_t)(3 * 16 * XPAD + 3 * 32 * Hz) * sizeof(float);
    size_t sbsm  = (size_t)(32 * 32 + 256 * 33 + 32 * 257) * sizeof(float);
    size_t relsm = (size_t)(64 * TST + 128 + 64 + 64 + 4 + 4) * sizeof(float);
    size_t cbsm  = (size_t)(128 * 33 + 16 * 130 + 192) * sizeof(float);
    size_t ctxsm = (size_t)(256 * 33 + 16 * 256 + 64) * sizeof(float);
    size_t outsm = (size_t)(Hz * Hz + 16 * Hz) * sizeof(float);
    cudaFuncSetAttribute(proj_kernel,    cudaFuncAttributeMaxDynamicSharedMemorySize, (int)prsm);
    cudaFuncSetAttribute(sbase_kernel,   cudaFuncAttributeMaxDynamicSharedMemorySize, (int)sbsm);
    cudaFuncSetAttribute(rel_kernel,     cudaFuncAttributeMaxDynamicSharedMemorySize, (int)relsm);
    cudaFuncSetAttribute(combine_kernel, cudaFuncAttributeMaxDynamicSharedMemorySize, (int)cbsm);
    cudaFuncSetAttribute(ctxv_kernel,    cudaFuncAttributeMaxDynamicSharedMemorySize, (int)ctxsm);
    cudaFuncSetAttribute(out_kernel,     cudaFuncAttributeMaxDynamicSharedMemorySize, (int)outsm);

    proj_kernel<<<BSz / 16, 256, prsm>>>(X, abs0, abs1, Wq, bq, Wk, bk, Wv, bv);
    dim3 gs(8, Bz, 4);
    sbase_kernel<<<gs, 256, sbsm>>>(mask, Wk);
    dim3 gr(Sz, Bz, 8);                        // z = i*4 + quarter
    rel_kernel<<<gr, 128, relsm>>>(rel0, rel1);
    dim3 gc(16, Bz, 2);
    combine_kernel<<<gc, 256, cbsm>>>(Wv, bv);
    dim3 gv(16, Bz, 4);
    ctxv_kernel<<<gv, 256, ctxsm>>>();
    out_kernel<<<BSz / 16, 256, outsm>>>(Wo, bo, out);
}